// round 3
// baseline (speedup 1.0000x reference)
#include <cuda_runtime.h>
#include <math.h>

#define NTOK   8192
#define NPAIR  (NTOK * 2)
#define NE     64
#define TPB    16
#define MAXCHUNK (NPAIR / TPB + NE)   // 1088

// ---- scratch (device globals; no allocs allowed) ----
__device__ float g_h[(size_t)NTOK * 4096];        // 134 MB
__device__ float g_yup[(size_t)NPAIR * 4096];     // 268 MB
__device__ float g_ydown[(size_t)NPAIR * 1024];   // 67 MB
__device__ float g_logits[(size_t)NTOK * NE];     // 2 MB
__device__ float g_prob[NPAIR];
__device__ int   g_cnt[NE];
__device__ int   g_list[NE * NPAIR];              // 4 MB
__device__ int2  g_chunk[MAXCHUNK];
__device__ int   g_nchunks;

__device__ __forceinline__ float gelu_erf(float v) { return v * normcdff(v); }

// ---------------------------------------------------------------------------
// Router GEMM v2: logits[M,64] = X[M,K] * W[64,K]^T. 128-token tiles, 256 thr.
// X staged natural [m][k] pad-33 (distinct-m scalar reads: 1 wf).
// W staged transposed [k][e] pad-68 (uniform float4 reads: broadcast).
// Per k: 4 distinct scalars + 2 uniform float4 = 6 wf per 32 FFMA.
// ---------------------------------------------------------------------------
template<int K>
__global__ __launch_bounds__(256) void router_gemm(
    const float* __restrict__ X, const float* __restrict__ W)
{
    __shared__ float sX[128][33];    // [m][k]
    __shared__ float sWT[32][68];    // [k][e]
    const int tid  = threadIdx.x;
    const int lane = tid & 31;
    const int warp = tid >> 5;
    if (blockIdx.x == 0 && tid < NE) g_cnt[tid] = 0;   // reset for top2

    const int m0 = blockIdx.x * 128;
    const int eb = warp * 8;

    float acc[4][8];
    #pragma unroll
    for (int i = 0; i < 4; i++)
        #pragma unroll
        for (int j = 0; j < 8; j++) acc[i][j] = 0.f;

    for (int kc = 0; kc < K; kc += 32) {
        // stage X: 128x32 = 1024 float4, 4 per thread
        #pragma unroll
        for (int rr = 0; rr < 4; rr++) {
            int f = tid + 256 * rr;
            int m = f >> 3, kl = (f & 7) * 4;
            float4 v = __ldg((const float4*)&X[(size_t)(m0 + m) * K + kc + kl]);
            sX[m][kl]     = v.x;
            sX[m][kl + 1] = v.y;
            sX[m][kl + 2] = v.z;
            sX[m][kl + 3] = v.w;
        }
        // stage W transposed: 64x32 = 512 float4, 2 per thread
        #pragma unroll
        for (int rr = 0; rr < 2; rr++) {
            int f = tid + 256 * rr;
            int e = f >> 3, kl = (f & 7) * 4;
            float4 v = __ldg((const float4*)&W[(size_t)e * K + kc + kl]);
            sWT[kl][e]     = v.x;
            sWT[kl + 1][e] = v.y;
            sWT[kl + 2][e] = v.z;
            sWT[kl + 3][e] = v.w;
        }
        __syncthreads();
        #pragma unroll
        for (int k = 0; k < 32; k++) {
            float xm[4];
            #pragma unroll
            for (int mm = 0; mm < 4; mm++) xm[mm] = sX[lane + 32 * mm][k];
            float4 w0 = *(const float4*)&sWT[k][eb];
            float4 w1 = *(const float4*)&sWT[k][eb + 4];
            #pragma unroll
            for (int mm = 0; mm < 4; mm++) {
                acc[mm][0] += xm[mm] * w0.x;
                acc[mm][1] += xm[mm] * w0.y;
                acc[mm][2] += xm[mm] * w0.z;
                acc[mm][3] += xm[mm] * w0.w;
                acc[mm][4] += xm[mm] * w1.x;
                acc[mm][5] += xm[mm] * w1.y;
                acc[mm][6] += xm[mm] * w1.z;
                acc[mm][7] += xm[mm] * w1.w;
            }
        }
        __syncthreads();
    }
    #pragma unroll
    for (int mm = 0; mm < 4; mm++) {
        float* lg = &g_logits[(size_t)(m0 + lane + 32 * mm) * NE + eb];
        *(float4*)lg       = make_float4(acc[mm][0], acc[mm][1], acc[mm][2], acc[mm][3]);
        *(float4*)(lg + 4) = make_float4(acc[mm][4], acc[mm][5], acc[mm][6], acc[mm][7]);
    }
}

// ---------------------------------------------------------------------------
// Top-2 + softmax + per-expert list build.  One warp per token.
// ---------------------------------------------------------------------------
__global__ __launch_bounds__(256) void top2_kernel()
{
    const int t    = blockIdx.x * 8 + (threadIdx.x >> 5);
    const int lane = threadIdx.x & 31;
    const float* lg = &g_logits[(size_t)t * NE];
    float v0 = lg[lane], v1 = lg[lane + 32];

    float m1; int i1;
    if (v0 >= v1) { m1 = v0; i1 = lane; } else { m1 = v1; i1 = lane + 32; }
    #pragma unroll
    for (int off = 16; off > 0; off >>= 1) {
        float om = __shfl_xor_sync(0xffffffffu, m1, off);
        int   oi = __shfl_xor_sync(0xffffffffu, i1, off);
        if (om > m1 || (om == m1 && oi < i1)) { m1 = om; i1 = oi; }
    }
    float c0 = (lane == i1)      ? -INFINITY : v0;
    float c1 = (lane + 32 == i1) ? -INFINITY : v1;
    float m2; int i2;
    if (c0 >= c1) { m2 = c0; i2 = lane; } else { m2 = c1; i2 = lane + 32; }
    #pragma unroll
    for (int off = 16; off > 0; off >>= 1) {
        float om = __shfl_xor_sync(0xffffffffu, m2, off);
        int   oi = __shfl_xor_sync(0xffffffffu, i2, off);
        if (om > m2 || (om == m2 && oi < i2)) { m2 = om; i2 = oi; }
    }
    if (lane == 0) {
        float p1 = 1.f / (1.f + expf(m2 - m1));
        g_prob[2 * t]     = p1;
        g_prob[2 * t + 1] = 1.f - p1;
        int pos = atomicAdd(&g_cnt[i1], 1);
        g_list[i1 * NPAIR + pos] = 2 * t;
        pos = atomicAdd(&g_cnt[i2], 1);
        g_list[i2 * NPAIR + pos] = 2 * t + 1;
    }
}

// ---------------------------------------------------------------------------
// Chunk map
// ---------------------------------------------------------------------------
__global__ void prefix_kernel()
{
    __shared__ int s_c[NE];
    __shared__ int s_off[NE];
    const int e = threadIdx.x;     // 64 threads
    int c = (g_cnt[e] + TPB - 1) / TPB;
    s_c[e] = c;
    __syncthreads();
    if (e == 0) {
        int s = 0;
        for (int i = 0; i < NE; i++) { s_off[i] = s; s += s_c[i]; }
        g_nchunks = s;
    }
    __syncthreads();
    int o = s_off[e];
    for (int i = 0; i < c; i++)
        g_chunk[o + i] = make_int2(e, i * TPB);
}

// ---------------------------------------------------------------------------
// Up bilinear v2: 2 pairs per iteration.
// T(64x32) = A(64x32) X(32x32);  Y(64x64) = T B^T
// T phase: o = {lane,lane+32} distinct scalar; j uniform float4. 4wf/16 FFMA.
// Y phase: p = {lane,lane+32} distinct scalar; o uniform float4. 6wf/32 FFMA.
// ---------------------------------------------------------------------------
__global__ __launch_bounds__(256) void bilinear_up(
    const float* __restrict__ x, const float* __restrict__ A, const float* __restrict__ B)
{
    const int b = blockIdx.x;
    if (b >= g_nchunks) return;
    const int2 ch   = g_chunk[b];
    const int e     = ch.x;
    const int start = ch.y;
    const int cnt   = g_cnt[e];
    const int tid   = threadIdx.x;
    const int lane  = tid & 31;
    const int warp  = tid >> 5;

    __shared__ float sAT[32][65];      // [i][o]  pad-65: transpose stores conflict-free
    __shared__ float sBT[32][65];      // [j][p]
    __shared__ float sX[2][32][32];    // [i][j] natural
    __shared__ float sTT[2][32][64];   // [j][o]

    // stage A [64][32] -> sAT[i][o], B -> sBT[j][p]
    {
        const float4* a4 = (const float4*)(A + (size_t)e * 2048);
        const float4* b4 = (const float4*)(B + (size_t)e * 2048);
        #pragma unroll
        for (int rr = 0; rr < 2; rr++) {
            int f   = tid + 256 * rr;
            int row = f >> 3;            // o or p
            int col = (f & 7) * 4;       // i or j
            float4 av = __ldg(&a4[f]);
            sAT[col][row] = av.x; sAT[col+1][row] = av.y;
            sAT[col+2][row] = av.z; sAT[col+3][row] = av.w;
            float4 bv = __ldg(&b4[f]);
            sBT[col][row] = bv.x; sBT[col+1][row] = bv.y;
            sBT[col+2][row] = bv.z; sBT[col+3][row] = bv.w;
        }
    }

    const int jb = warp * 4;   // T phase: 4 j's (8 warps cover 32)
    const int ob = warp * 8;   // Y phase: 8 o's (8 warps cover 64)
    const int xi = tid >> 3;
    const int xj = (tid & 7) * 4;

    __syncthreads();

    for (int u = 0; u < TPB; u += 2) {
        int pi0 = start + u;
        if (pi0 >= cnt) break;                 // block-uniform
        int  pair0  = g_list[e * NPAIR + pi0];
        bool valid1 = (pi0 + 1 < cnt);
        int  pair1  = valid1 ? g_list[e * NPAIR + pi0 + 1] : pair0;
        int  t0 = pair0 >> 1, t1 = pair1 >> 1;

        // stage X for both pairs (contiguous float4 STS)
        float4 xv0 = __ldg((const float4*)&x[(size_t)t0 * 1024 + tid * 4]);
        float4 xv1 = __ldg((const float4*)&x[(size_t)t1 * 1024 + tid * 4]);
        *(float4*)&sX[0][xi][xj] = xv0;
        *(float4*)&sX[1][xi][xj] = xv1;
        __syncthreads();

        // ---- T phase ----
        {
            float tacc[2][2][4];
            #pragma unroll
            for (int p = 0; p < 2; p++)
                #pragma unroll
                for (int s = 0; s < 2; s++)
                    #pragma unroll
                    for (int j = 0; j < 4; j++) tacc[p][s][j] = 0.f;
            #pragma unroll
            for (int i = 0; i < 32; i++) {
                float a0 = sAT[i][lane];
                float a1 = sAT[i][lane + 32];
                float4 x0 = *(const float4*)&sX[0][i][jb];
                float4 x1 = *(const float4*)&sX[1][i][jb];
                tacc[0][0][0] += a0*x0.x; tacc[0][0][1] += a0*x0.y; tacc[0][0][2] += a0*x0.z; tacc[0][0][3] += a0*x0.w;
                tacc[0][1][0] += a1*x0.x; tacc[0][1][1] += a1*x0.y; tacc[0][1][2] += a1*x0.z; tacc[0][1][3] += a1*x0.w;
                tacc[1][0][0] += a0*x1.x; tacc[1][0][1] += a0*x1.y; tacc[1][0][2] += a0*x1.z; tacc[1][0][3] += a0*x1.w;
                tacc[1][1][0] += a1*x1.x; tacc[1][1][1] += a1*x1.y; tacc[1][1][2] += a1*x1.z; tacc[1][1][3] += a1*x1.w;
            }
            #pragma unroll
            for (int p = 0; p < 2; p++)
                #pragma unroll
                for (int jj = 0; jj < 4; jj++) {
                    sTT[p][jb + jj][lane]      = tacc[p][0][jj];
                    sTT[p][jb + jj][lane + 32] = tacc[p][1][jj];
                }
        }
        __syncthreads();

        // ---- Y phase ----
        {
            float y[2][2][8];
            #pragma unroll
            for (int p = 0; p < 2; p++)
                #pragma unroll
                for (int s = 0; s < 2; s++)
                    #pragma unroll
                    for (int oo = 0; oo < 8; oo++) y[p][s][oo] = 0.f;
            #pragma unroll
            for (int j = 0; j < 32; j++) {
                float b0 = sBT[j][lane];
                float b1 = sBT[j][lane + 32];
                float4 ta0 = *(const float4*)&sTT[0][j][ob];
                float4 tb0 = *(const float4*)&sTT[0][j][ob + 4];
                float4 ta1 = *(const float4*)&sTT[1][j][ob];
                float4 tb1 = *(const float4*)&sTT[1][j][ob + 4];
                y[0][0][0] += ta0.x*b0; y[0][0][1] += ta0.y*b0; y[0][0][2] += ta0.z*b0; y[0][0][3] += ta0.w*b0;
                y[0][0][4] += tb0.x*b0; y[0][0][5] += tb0.y*b0; y[0][0][6] += tb0.z*b0; y[0][0][7] += tb0.w*b0;
                y[0][1][0] += ta0.x*b1; y[0][1][1] += ta0.y*b1; y[0][1][2] += ta0.z*b1; y[0][1][3] += ta0.w*b1;
                y[0][1][4] += tb0.x*b1; y[0][1][5] += tb0.y*b1; y[0][1][6] += tb0.z*b1; y[0][1][7] += tb0.w*b1;
                y[1][0][0] += ta1.x*b0; y[1][0][1] += ta1.y*b0; y[1][0][2] += ta1.z*b0; y[1][0][3] += ta1.w*b0;
                y[1][0][4] += tb1.x*b0; y[1][0][5] += tb1.y*b0; y[1][0][6] += tb1.z*b0; y[1][0][7] += tb1.w*b0;
                y[1][1][0] += ta1.x*b1; y[1][1][1] += ta1.y*b1; y[1][1][2] += ta1.z*b1; y[1][1][3] += ta1.w*b1;
                y[1][1][4] += tb1.x*b1; y[1][1][5] += tb1.y*b1; y[1][1][6] += tb1.z*b1; y[1][1][7] += tb1.w*b1;
            }
            // coalesced scalar stores: lanes contiguous in p
            float* y0 = &g_yup[(size_t)pair0 * 4096];
            #pragma unroll
            for (int oo = 0; oo < 8; oo++) {
                y0[(ob + oo) * 64 + lane]      = y[0][0][oo];
                y0[(ob + oo) * 64 + lane + 32] = y[0][1][oo];
            }
            if (valid1) {
                float* y1 = &g_yup[(size_t)pair1 * 4096];
                #pragma unroll
                for (int oo = 0; oo < 8; oo++) {
                    y1[(ob + oo) * 64 + lane]      = y[1][0][oo];
                    y1[(ob + oo) * 64 + lane + 32] = y[1][1][oo];
                }
            }
        }
        __syncthreads();
    }
}

// ---------------------------------------------------------------------------
// Down bilinear v2: 2 pairs per iteration.
// T(32x64) = A(32x64) H(64x64);  Y(32x32) = T B^T
// ---------------------------------------------------------------------------
__global__ __launch_bounds__(256) void bilinear_down(
    const float* __restrict__ A, const float* __restrict__ B)
{
    const int b = blockIdx.x;
    if (b >= g_nchunks) return;
    const int2 ch   = g_chunk[b];
    const int e     = ch.x;
    const int start = ch.y;
    const int cnt   = g_cnt[e];
    const int tid   = threadIdx.x;
    const int lane  = tid & 31;
    const int warp  = tid >> 5;

    __shared__ float sAT[64][33];      // [i][o<32]
    __shared__ float sBT[64][33];      // [j][p<32]
    __shared__ float sH[2][64][64];    // [i][j] natural, 32KB
    __shared__ float sTT[2][64][32];   // [j][o], 16KB

    // stage A [32][64] -> sAT[i][o], B -> sBT[j][p]
    {
        const float4* a4 = (const float4*)(A + (size_t)e * 2048);
        const float4* b4 = (const float4*)(B + (size_t)e * 2048);
        #pragma unroll
        for (int rr = 0; rr < 2; rr++) {
            int f   = tid + 256 * rr;
            int row = f >> 4;            // o or p  (<32)
            int col = (f & 15) * 4;      // i or j
            float4 av = __ldg(&a4[f]);
            sAT[col][row] = av.x; sAT[col+1][row] = av.y;
            sAT[col+2][row] = av.z; sAT[col+3][row] = av.w;
            float4 bv = __ldg(&b4[f]);
            sBT[col][row] = bv.x; sBT[col+1][row] = bv.y;
            sBT[col+2][row] = bv.z; sBT[col+3][row] = bv.w;
        }
    }

    const int jb = warp * 8;   // T phase: 8 j's (8 warps cover 64)
    const int ob = warp * 4;   // Y phase: 4 o's (8 warps cover 32)

    __syncthreads();

    for (int u = 0; u < TPB; u += 2) {
        int pi0 = start + u;
        if (pi0 >= cnt) break;
        int  pair0  = g_list[e * NPAIR + pi0];
        bool valid1 = (pi0 + 1 < cnt);
        int  pair1  = valid1 ? g_list[e * NPAIR + pi0 + 1] : pair0;
        int  t0 = pair0 >> 1, t1 = pair1 >> 1;

        // stage H for both pairs (contiguous float4)
        {
            const float4* h0 = (const float4*)&g_h[(size_t)t0 * 4096];
            const float4* h1 = (const float4*)&g_h[(size_t)t1 * 4096];
            #pragma unroll
            for (int rr = 0; rr < 4; rr++) {
                int f = tid + 256 * rr;
                *(float4*)&sH[0][f >> 4][(f & 15) * 4] = __ldg(&h0[f]);
                *(float4*)&sH[1][f >> 4][(f & 15) * 4] = __ldg(&h1[f]);
            }
        }
        __syncthreads();

        // ---- T phase: o = lane (distinct), 8 j uniform ----
        {
            float tacc[2][8];
            #pragma unroll
            for (int p = 0; p < 2; p++)
                #pragma unroll
                for (int j = 0; j < 8; j++) tacc[p][j] = 0.f;
            #pragma unroll
            for (int i = 0; i < 64; i++) {
                float a = sAT[i][lane];
                float4 h0a = *(const float4*)&sH[0][i][jb];
                float4 h0b = *(const float4*)&sH[0][i][jb + 4];
                float4 h1a = *(const float4*)&sH[1][i][jb];
                float4 h1b = *(const float4*)&sH[1][i][jb + 4];
                tacc[0][0] += a*h0a.x; tacc[0][1] += a*h0a.y; tacc[0][2] += a*h0a.z; tacc[0][3] += a*h0a.w;
                tacc[0][4] += a*h0b.x; tacc[0][5] += a*h0b.y; tacc[0][6] += a*h0b.z; tacc[0][7] += a*h0b.w;
                tacc[1][0] += a*h1a.x; tacc[1][1] += a*h1a.y; tacc[1][2] += a*h1a.z; tacc[1][3] += a*h1a.w;
                tacc[1][4] += a*h1b.x; tacc[1][5] += a*h1b.y; tacc[1][6] += a*h1b.z; tacc[1][7] += a*h1b.w;
            }
            #pragma unroll
            for (int p = 0; p < 2; p++)
                #pragma unroll
                for (int jj = 0; jj < 8; jj++)
                    sTT[p][jb + jj][lane] = tacc[p][jj];
        }
        __syncthreads();

        // ---- Y phase: p = lane (distinct), 4 o uniform ----
        {
            float y[2][4];
            #pragma unroll
            for (int p = 0; p < 2; p++)
                #pragma unroll
                for (int oo = 0; oo < 4; oo++) y[p][oo] = 0.f;
            #pragma unroll
            for (int j = 0; j < 64; j++) {
                float bv = sBT[j][lane];
                float4 t0v = *(const float4*)&sTT[0][j][ob];
                float4 t1v = *(const float4*)&sTT[1][j][ob];
                y[0][0] += t0v.x*bv; y[0][1] += t0v.y*bv; y[0][2] += t0v.z*bv; y[0][3] += t0v.w*bv;
                y[1][0] += t1v.x*bv; y[1][1] += t1v.y*bv; y[1][2] += t1v.z*bv; y[1][3] += t1v.w*bv;
            }
            float* yo0 = &g_ydown[(size_t)pair0 * 1024];
            #pragma unroll
            for (int oo = 0; oo < 4; oo++)
                yo0[(ob + oo) * 32 + lane] = y[0][oo];
            if (valid1) {
                float* yo1 = &g_ydown[(size_t)pair1 * 1024];
                #pragma unroll
                for (int oo = 0; oo < 4; oo++)
                    yo1[(ob + oo) * 32 + lane] = y[1][oo];
            }
        }
        __syncthreads();
    }
}

// ---------------------------------------------------------------------------
// Combine kernels
// ---------------------------------------------------------------------------
__global__ __launch_bounds__(256) void combine_up(
    const float* __restrict__ scale, const float* __restrict__ bias)
{
    const int t   = blockIdx.x;
    const int tid = threadIdx.x;
    const float p0 = g_prob[2 * t], p1 = g_prob[2 * t + 1];
    const float s  = __ldg(scale);
    const float4* y0 = (const float4*)&g_yup[(size_t)(2 * t) * 4096];
    const float4* y1 = (const float4*)&g_yup[(size_t)(2 * t + 1) * 4096];
    const float4* b4 = (const float4*)bias;
    float4* h4 = (float4*)&g_h[(size_t)t * 4096];
    #pragma unroll
    for (int rr = 0; rr < 4; rr++) {
        int f = tid + 256 * rr;
        float4 a = __ldg(&y0[f]), c = __ldg(&y1[f]), bb = __ldg(&b4[f]);
        float4 v;
        v.x = gelu_erf(s * (p0 * a.x + p1 * c.x) + bb.x);
        v.y = gelu_erf(s * (p0 * a.y + p1 * c.y) + bb.y);
        v.z = gelu_erf(s * (p0 * a.z + p1 * c.z) + bb.z);
        v.w = gelu_erf(s * (p0 * a.w + p1 * c.w) + bb.w);
        h4[f] = v;
    }
}

__global__ __launch_bounds__(256) void combine_down(
    const float* __restrict__ scale, const float* __restrict__ bias,
    float* __restrict__ out)
{
    const int t   = blockIdx.x;
    const int tid = threadIdx.x;
    const float p0 = g_prob[2 * t], p1 = g_prob[2 * t + 1];
    const float s  = __ldg(scale);
    const float4* y0 = (const float4*)&g_ydown[(size_t)(2 * t) * 1024];
    const float4* y1 = (const float4*)&g_ydown[(size_t)(2 * t + 1) * 1024];
    const float4* b4 = (const float4*)bias;
    float4 a = __ldg(&y0[tid]), c = __ldg(&y1[tid]), bb = __ldg(&b4[tid]);
    float4 v;
    v.x = s * (p0 * a.x + p1 * c.x) + bb.x;
    v.y = s * (p0 * a.y + p1 * c.y) + bb.y;
    v.z = s * (p0 * a.z + p1 * c.z) + bb.z;
    v.w = s * (p0 * a.w + p1 * c.w) + bb.w;
    ((float4*)&out[(size_t)t * 1024])[tid] = v;
}

// ---------------------------------------------------------------------------
extern "C" void kernel_launch(void* const* d_in, const int* in_sizes, int n_in,
                              void* d_out, int out_size)
{
    const float* x          = (const float*)d_in[0];
    const float* W_up       = (const float*)d_in[1];
    const float* A_up       = (const float*)d_in[2];
    const float* B_up       = (const float*)d_in[3];
    const float* scale_up   = (const float*)d_in[4];
    const float* bias_up    = (const float*)d_in[5];
    const float* W_down     = (const float*)d_in[6];
    const float* A_down     = (const float*)d_in[7];
    const float* B_down     = (const float*)d_in[8];
    const float* scale_down = (const float*)d_in[9];
    const float* bias_down  = (const float*)d_in[10];
    float*       out        = (float*)d_out;

    const int n_tok = in_sizes[0] / 1024;     // 8192

    float* h_ptr = nullptr;
    cudaGetSymbolAddress((void**)&h_ptr, g_h);

    // ---- up ----
    router_gemm<1024><<<n_tok / 128, 256>>>(x, W_up);
    top2_kernel<<<n_tok / 8, 256>>>();
    prefix_kernel<<<1, 64>>>();
    bilinear_up<<<MAXCHUNK, 256>>>(x, A_up, B_up);
    combine_up<<<n_tok, 256>>>(scale_up, bias_up);

    // ---- down ----
    router_gemm<4096><<<n_tok / 128, 256>>>(h_ptr, W_down);
    top2_kernel<<<n_tok / 8, 256>>>();
    prefix_kernel<<<1, 64>>>();
    bilinear_down<<<MAXCHUNK, 256>>>(A_down, B_down);
    combine_down<<<n_tok, 256>>>(scale_down, bias_down, out);
}